// round 4
// baseline (speedup 1.0000x reference)
#include <cuda_runtime.h>
#include <math_constants.h>

#define D_FEAT   128
#define K_NEIGH  32
#define WARPS_PER_CTA 4

// One WARP per batch item, no shared memory.
//
// Sim phase (as R3): 4 rows per pass, 8-lane-group reduction so each shuffle
// instruction serves 4 rows. Ranking key = dot * rsqrt(||n||^2) (center norm
// cancels for top-k).
//
// Selection (new): single-pass rank. Each lane computes
//   rank_i = #{j: s_j > s_i} + #{j<i: s_j == s_i}
// with 32 INDEPENDENT broadcast shuffles (no serial argmax chain). Ranks are a
// permutation of 0..31 (tie -> lower index = jax.lax.top_k stability), so
// ballot(rank < ns) has exactly ns bits; winner rows are gathered back-to-back
// with full MLP (L1/L2-hot lines).
__global__ __launch_bounds__(WARPS_PER_CTA * 32, 10)
void intra_agg_kernel(const float*  __restrict__ feats,
                      const int*    __restrict__ nodes,
                      const int*    __restrict__ neighs,
                      const int*    __restrict__ nsamp_p,
                      float*        __restrict__ out)
{
    const int lane = threadIdx.x & 31;
    const int warp = threadIdx.x >> 5;
    const int b    = blockIdx.x * WARPS_PER_CTA + warp;
    const int g    = lane >> 3;        // group 0..3  (which row of the quad)
    const int t    = lane & 7;         // lane within group

    const float4* __restrict__ f4 = reinterpret_cast<const float4*>(feats);

    // ---- center row: this lane's 16-float column slice ----
    const int node = nodes[b];
    float4 c[4];
    #pragma unroll
    for (int j = 0; j < 4; j++)
        c[j] = f4[(size_t)node * (D_FEAT / 4) + t + 8 * j];

    // ---- my neighbor index (one coalesced 128B load) ----
    const int my_idx = neighs[b * K_NEIGH + lane];

    // ---- similarities: 8 passes x 4 rows; lane k ends with sim of row k ----
    float my_sim = 0.0f;
    #pragma unroll
    for (int p = 0; p < K_NEIGH / 4; p++) {
        const int nidx = __shfl_sync(0xffffffffu, my_idx, 4 * p + g);
        const float4* __restrict__ row = f4 + (size_t)nidx * (D_FEAT / 4);

        float dot = 0.0f, ss = 0.0f;
        #pragma unroll
        for (int j = 0; j < 4; j++) {
            const float4 v = row[t + 8 * j];
            dot = fmaf(v.x, c[j].x, fmaf(v.y, c[j].y,
                  fmaf(v.z, c[j].z, fmaf(v.w, c[j].w, dot))));
            ss  = fmaf(v.x, v.x, fmaf(v.y, v.y,
                  fmaf(v.z, v.z, fmaf(v.w, v.w, ss))));
        }
        // 3-stage butterfly within each 8-lane group (serves 4 rows at once)
        #pragma unroll
        for (int off = 1; off < 8; off <<= 1) {
            dot += __shfl_xor_sync(0xffffffffu, dot, off);
            ss  += __shfl_xor_sync(0xffffffffu, ss,  off);
        }
        const float s = dot * rsqrtf(ss);
        // route: row 4p+g' was reduced in group g' (lanes 8g'..8g'+7)
        const float sv = __shfl_sync(0xffffffffu, s, (lane & 3) * 8);
        if ((lane >> 2) == p) my_sim = sv;
    }

    const int ns = nsamp_p ? *nsamp_p : 10;

    // ---- single-pass rank selection (32 independent shuffles) ----
    int rank = 0;
    #pragma unroll
    for (int j = 0; j < K_NEIGH; j++) {
        const float sj = __shfl_sync(0xffffffffu, my_sim, j);
        rank += (sj > my_sim) | ((sj == my_sim) & (j < lane));
    }
    unsigned mask = __ballot_sync(0xffffffffu, rank < ns);  // exactly ns bits

    // ---- accumulate winner rows (independent gathers, full MLP) ----
    float4 acc = make_float4(0.0f, 0.0f, 0.0f, 0.0f);
    for (int i = 0; i < ns; i++) {
        const int w = __ffs(mask) - 1;
        mask &= mask - 1;
        const int nidx = __shfl_sync(0xffffffffu, my_idx, w);
        const float4 v = f4[(size_t)nidx * (D_FEAT / 4) + lane];
        acc.x += v.x; acc.y += v.y; acc.z += v.z; acc.w += v.w;
    }

    // ---- mean + relu, coalesced store ----
    const float inv = 1.0f / (float)ns;
    float4 r;
    r.x = fmaxf(acc.x * inv, 0.0f);
    r.y = fmaxf(acc.y * inv, 0.0f);
    r.z = fmaxf(acc.z * inv, 0.0f);
    r.w = fmaxf(acc.w * inv, 0.0f);
    reinterpret_cast<float4*>(out)[(size_t)b * (D_FEAT / 4) + lane] = r;
}

extern "C" void kernel_launch(void* const* d_in, const int* in_sizes, int n_in,
                              void* d_out, int out_size)
{
    const float* feats  = (const float*)d_in[0];   // [N_NODES, 128] f32
    const int*   nodes  = (const int*)d_in[1];     // [B] i32
    const int*   neighs = (const int*)d_in[2];     // [B, 32] i32
    const int*   nsamp  = (n_in > 3) ? (const int*)d_in[3] : nullptr;  // scalar (10)

    const int B = in_sizes[1];                     // 32768
    intra_agg_kernel<<<B / WARPS_PER_CTA, WARPS_PER_CTA * 32>>>(
        feats, nodes, neighs, nsamp, (float*)d_out);
}